// round 7
// baseline (speedup 1.0000x reference)
#include <cuda_runtime.h>
#include <cuda_bf16.h>
#include <cstdint>

// Embedding gather: out[s, :] = weights[x[s], :]
// x: [8192] int32, weights: [49408, 768] fp32, out: [8192, 768] fp32
//
// L2 residency control: the replayed gather set (~23 MB unique rows) is pinned
// with evict_last; output writes leave early with evict_first. sm_103a only
// allows these hints on 256-bit accesses, so each thread moves 32 B (.v4.b64).
// Row = 3072 B = 96 chunks of 32 B. Block = 192 threads = 2 rows per step,
// U = 8 rows per CTA -> 4 steps, 4 independent 32 B loads in flight/thread.

#define SEQ    8192
#define ROWQW  96          // 32B chunks per row
#define BLK    192
#define U      8           // rows per CTA
#define STEPS  (U / 2)     // 2 rows per step

__device__ __forceinline__ ulonglong4 ldg_pin_l2(const void* p) {
    ulonglong4 v;
    asm("ld.global.nc.L2::evict_last.v4.u64 {%0,%1,%2,%3}, [%4];"
        : "=l"(v.x), "=l"(v.y), "=l"(v.z), "=l"(v.w) : "l"(p));
    return v;
}

__device__ __forceinline__ void stg_evict_first(void* p, ulonglong4 v) {
    asm volatile("st.global.L2::evict_first.v4.u64 [%0], {%1,%2,%3,%4};"
                 :: "l"(p), "l"(v.x), "l"(v.y), "l"(v.z), "l"(v.w) : "memory");
}

__global__ void __launch_bounds__(BLK) embed_gather_kernel(
    const int* __restrict__ x,
    const ulonglong4* __restrict__ weights,   // [VOCAB, ROWQW]
    ulonglong4* __restrict__ out)             // [SEQ, ROWQW]
{
    const int t  = threadIdx.x;
    const int r  = t / ROWQW;     // 0 or 1: which row of the pair
    const int c  = t % ROWQW;     // chunk within row
    const int s0 = blockIdx.x * U;

    int rows[STEPS];
#pragma unroll
    for (int i = 0; i < STEPS; i++)
        rows[i] = __ldg(&x[s0 + i * 2 + r]);

    ulonglong4 v[STEPS];
#pragma unroll
    for (int i = 0; i < STEPS; i++)
        v[i] = ldg_pin_l2(&weights[(size_t)rows[i] * ROWQW + c]);

#pragma unroll
    for (int i = 0; i < STEPS; i++)
        stg_evict_first(&out[(size_t)(s0 + i * 2 + r) * ROWQW + c], v[i]);
}

extern "C" void kernel_launch(void* const* d_in, const int* in_sizes, int n_in,
                              void* d_out, int out_size) {
    const int*        x = (const int*)d_in[0];
    const ulonglong4* w = (const ulonglong4*)d_in[1];
    ulonglong4*       o = (ulonglong4*)d_out;
    embed_gather_kernel<<<SEQ / U, BLK>>>(x, w, o);
}